// round 3
// baseline (speedup 1.0000x reference)
#include <cuda_runtime.h>
#include <math.h>
#include <float.h>

#define N_PTS 4096
#define BATCH 4
#define C_IN  64
#define C_OUT 128
#define KNN   20
#define C_BOT 16
#define EPSBN 1e-5f

// ---------------- scratch (device globals; no allocation) ----------------
__device__ float g_sq[BATCH * N_PTS];                       // 64 KB
__device__ float g_hb[BATCH * N_PTS * C_BOT];               // 1 MB, [B,N,16]
__device__ float g_d2[(size_t)BATCH * N_PTS * N_PTS];       // 256 MiB
__device__ int   g_idx[BATCH * N_PTS * KNN];                // 5 MB

// ---------------- K1: sq norms + bottleneck conv (BN+ReLU), hb transposed ----
__global__ void k_prep(const float* __restrict__ x,
                       const float* __restrict__ Wb, const float* __restrict__ gb,
                       const float* __restrict__ bb, const float* __restrict__ mb,
                       const float* __restrict__ vb)
{
    __shared__ float sW[C_BOT][C_IN];
    __shared__ float sS[C_BOT], sT[C_BOT];
    int tid = threadIdx.x;
    if (tid < C_BOT) {
        float s = gb[tid] * rsqrtf(vb[tid] + EPSBN);
        sS[tid] = s;
        sT[tid] = bb[tid] - mb[tid] * s;
    }
    for (int e = tid; e < C_BOT * C_IN; e += blockDim.x)
        sW[e >> 6][e & 63] = Wb[e];
    __syncthreads();

    int g = blockIdx.x * blockDim.x + tid;      // 0 .. BATCH*N_PTS-1
    if (g >= BATCH * N_PTS) return;
    int b = g >> 12, n = g & (N_PTS - 1);
    const float* xp = x + (size_t)b * C_IN * N_PTS + n;

    float xc[C_IN];
    float sq = 0.f;
#pragma unroll
    for (int c = 0; c < C_IN; c++) {
        float v = xp[(size_t)c * N_PTS];
        xc[c] = v;
        sq += v * v;                 // same ascending-c order as GEMM dot
    }
    g_sq[g] = sq;

#pragma unroll
    for (int o = 0; o < C_BOT; o++) {
        float acc = 0.f;
#pragma unroll
        for (int c = 0; c < C_IN; c++) acc += sW[o][c] * xc[c];
        float h = acc * sS[o] + sT[o];
        g_hb[(size_t)g * C_BOT + o] = fmaxf(h, 0.f);
    }
}

// ---------------- K2: pairwise squared distances (tiled fp32 GEMM) ----------
__global__ void k_dist(const float* __restrict__ x)
{
    __shared__ float As[64][64];
    __shared__ float Bs[64][64];
    __shared__ float sqA[64], sqB[64];

    int b  = blockIdx.z;
    int bi = blockIdx.y;
    int bj = blockIdx.x;
    int tid = threadIdx.x;
    const float* xb = x + (size_t)b * C_IN * N_PTS;

    for (int e = tid; e < 64 * 64; e += 256) {
        int i = e & 63, k = e >> 6;
        As[k][i] = xb[(size_t)k * N_PTS + bi * 64 + i];
        Bs[k][i] = xb[(size_t)k * N_PTS + bj * 64 + i];
    }
    if (tid < 64)       sqA[tid]      = g_sq[b * N_PTS + bi * 64 + tid];
    else if (tid < 128) sqB[tid - 64] = g_sq[b * N_PTS + bj * 64 + (tid - 64)];
    __syncthreads();

    int tx = tid & 15, ty = tid >> 4;
    float acc[4][4] = {};
#pragma unroll 16
    for (int k = 0; k < 64; k++) {
        float a0 = As[k][ty * 4 + 0], a1 = As[k][ty * 4 + 1];
        float a2 = As[k][ty * 4 + 2], a3 = As[k][ty * 4 + 3];
        float b0 = Bs[k][tx * 4 + 0], b1 = Bs[k][tx * 4 + 1];
        float b2 = Bs[k][tx * 4 + 2], b3 = Bs[k][tx * 4 + 3];
        acc[0][0] += a0 * b0; acc[0][1] += a0 * b1; acc[0][2] += a0 * b2; acc[0][3] += a0 * b3;
        acc[1][0] += a1 * b0; acc[1][1] += a1 * b1; acc[1][2] += a1 * b2; acc[1][3] += a1 * b3;
        acc[2][0] += a2 * b0; acc[2][1] += a2 * b1; acc[2][2] += a2 * b2; acc[2][3] += a2 * b3;
        acc[3][0] += a3 * b0; acc[3][1] += a3 * b1; acc[3][2] += a3 * b2; acc[3][3] += a3 * b3;
    }

    float* dp = g_d2 + ((size_t)(b * N_PTS + bi * 64)) * N_PTS + bj * 64;
#pragma unroll
    for (int ri = 0; ri < 4; ri++) {
        int r = ty * 4 + ri;
        float sr = sqA[r];
        float4 v;
        v.x = sr + sqB[tx * 4 + 0] - 2.f * acc[ri][0];
        v.y = sr + sqB[tx * 4 + 1] - 2.f * acc[ri][1];
        v.z = sr + sqB[tx * 4 + 2] - 2.f * acc[ri][2];
        v.w = sr + sqB[tx * 4 + 3] - 2.f * acc[ri][3];
        *(float4*)(dp + (size_t)r * N_PTS + tx * 4) = v;
    }
}

// ---------------- K3: top-K (sorted ascending, tie -> lower index) -----------
__global__ void k_topk()
{
    __shared__ float sd[N_PTS];
    __shared__ unsigned long long warpmin[4];
    int row = blockIdx.x;                      // b*N + n
    const float* dp = g_d2 + (size_t)row * N_PTS;
    int tid = threadIdx.x;                     // 128 threads
    for (int e = tid; e < N_PTS / 4; e += 128)
        ((float4*)sd)[e] = ((const float4*)dp)[e];
    __syncthreads();

    int lane = tid & 31, w = tid >> 5;
    for (int j = 0; j < KNN; j++) {
        unsigned long long best = 0xFFFFFFFFFFFFFFFFULL;
        for (int e = tid; e < N_PTS; e += 128) {
            unsigned u = __float_as_uint(sd[e]);
            u = (u & 0x80000000u) ? ~u : (u | 0x80000000u);   // orderable key
            unsigned long long p = ((unsigned long long)u << 32) | (unsigned)e;
            if (p < best) best = p;
        }
#pragma unroll
        for (int s = 16; s; s >>= 1) {
            unsigned long long o = __shfl_down_sync(0xffffffffu, best, s);
            if (o < best) best = o;
        }
        if (lane == 0) warpmin[w] = best;
        __syncthreads();
        if (tid == 0) {
            unsigned long long m = warpmin[0];
            if (warpmin[1] < m) m = warpmin[1];
            if (warpmin[2] < m) m = warpmin[2];
            if (warpmin[3] < m) m = warpmin[3];
            int mi = (int)(m & 0xFFFFFFFFu);
            g_idx[row * KNN + j] = mi;
            sd[mi] = __int_as_float(0x7f800000);   // +inf
        }
        __syncthreads();
    }
}

// ---------------- K4: fused gather + 2x GCN + gmax + decoder + residual -----
#define NT 8          // points per block
#define PAD_RES 65
#define PAD_DEC 97
#define PAD_G   33

__global__ void k_final(const float* __restrict__ x,
                        const float* __restrict__ Wres, const float* __restrict__ gres,
                        const float* __restrict__ bres, const float* __restrict__ mres,
                        const float* __restrict__ vres,
                        const float* __restrict__ Wg1, const float* __restrict__ gg1,
                        const float* __restrict__ bg1, const float* __restrict__ mg1,
                        const float* __restrict__ vg1,
                        const float* __restrict__ Wg2, const float* __restrict__ gg2,
                        const float* __restrict__ bg2, const float* __restrict__ mg2,
                        const float* __restrict__ vg2,
                        const float* __restrict__ Wdec, const float* __restrict__ gdec,
                        const float* __restrict__ bdec, const float* __restrict__ mdec,
                        const float* __restrict__ vdec,
                        float* __restrict__ out)
{
    extern __shared__ float sm[];
    float* sWres = sm;                               // 128*65
    float* sWdec = sWres + 128 * PAD_RES;            // 128*97
    float* sWg1  = sWdec + 128 * PAD_DEC;            // 32*33
    float* sWg2  = sWg1 + 32 * PAD_G;                // 32*33
    float* sSres = sWg2 + 32 * PAD_G;                // 128
    float* tRes  = sSres + 128;                      // 128
    float* sSdec = tRes + 128;                       // 128
    float* tDec  = sSdec + 128;                      // 128
    float* sSg1  = tDec + 128;                       // 32
    float* tG1   = sSg1 + 32;                        // 32
    float* sSg2  = tG1 + 32;                         // 32
    float* tG2   = sSg2 + 32;                        // 32
    float* sX    = tG2 + 32;                         // 64
    float* sCtr  = sX + 64;                          // 16
    float* sNb   = sCtr + 16;                        // 20*17
    float* sAll  = sNb + 20 * 17;                    // 96
    float* sPm   = sAll + 96;                        // 256
    int*   sIdx  = (int*)(sPm + 256);                // 20

    int tid = threadIdx.x;                           // 128 threads
    int b = blockIdx.y;

    if (tid < 128) {
        float s = gres[tid] * rsqrtf(vres[tid] + EPSBN);
        sSres[tid] = s; tRes[tid] = bres[tid] - mres[tid] * s;
        s = gdec[tid] * rsqrtf(vdec[tid] + EPSBN);
        sSdec[tid] = s; tDec[tid] = bdec[tid] - mdec[tid] * s;
    }
    if (tid < 32) {
        float s = gg1[tid] * rsqrtf(vg1[tid] + EPSBN);
        sSg1[tid] = s; tG1[tid] = bg1[tid] - mg1[tid] * s;
        s = gg2[tid] * rsqrtf(vg2[tid] + EPSBN);
        sSg2[tid] = s; tG2[tid] = bg2[tid] - mg2[tid] * s;
    }
    __syncthreads();

    for (int e = tid; e < 128 * 64; e += 128) {
        int o = e >> 6, c = e & 63;
        sWres[o * PAD_RES + c] = Wres[e] * sSres[o];
    }
    for (int e = tid; e < 128 * 96; e += 128) {
        int o = e / 96, c = e - o * 96;
        sWdec[o * PAD_DEC + c] = Wdec[e] * sSdec[o];
    }
    for (int e = tid; e < 32 * 32; e += 128) {
        int o = e >> 5, c = e & 31;
        sWg1[o * PAD_G + c] = Wg1[e] * sSg1[o];
        sWg2[o * PAD_G + c] = Wg2[e] * sSg2[o];
    }
    __syncthreads();

    for (int nn = 0; nn < NT; nn++) {
        int n = blockIdx.x * NT + nn;
        int gr = b * N_PTS + n;

        if (tid < 64) sX[tid] = x[((size_t)(b * C_IN + tid)) * N_PTS + n];
        if (tid < 16) sCtr[tid] = g_hb[(size_t)gr * C_BOT + tid];
        if (tid >= 96 && tid < 96 + KNN) sIdx[tid - 96] = g_idx[gr * KNN + (tid - 96)];
        __syncthreads();
        for (int e = tid; e < KNN * C_BOT; e += 128) {
            int k = e >> 4, c = e & 15;
            sNb[k * 17 + c] = g_hb[((size_t)b * N_PTS + sIdx[k]) * C_BOT + c];
        }
        __syncthreads();

        // GCN branch 1 (all 20 neighbors) & branch 2 (positions 0,2,..,18)
        int o = tid & 31, g = tid >> 5;  // 4 groups
        float cd1 = tG1[o], cd2 = tG2[o];
#pragma unroll
        for (int c = 0; c < 16; c++) {
            cd1 += sWg1[o * PAD_G + 16 + c] * sCtr[c];
            cd2 += sWg2[o * PAD_G + 16 + c] * sCtr[c];
        }
        float m1 = -FLT_MAX;
        for (int k = g; k < KNN; k += 4) {
            float a = cd1;
#pragma unroll
            for (int c = 0; c < 16; c++) a += sWg1[o * PAD_G + c] * sNb[k * 17 + c];
            a = a > 0.f ? a : 0.2f * a;
            m1 = fmaxf(m1, a);
        }
        float m2 = -FLT_MAX;
        for (int j = g; j < KNN / 2; j += 4) {
            int k = 2 * j;
            float a = cd2;
#pragma unroll
            for (int c = 0; c < 16; c++) a += sWg2[o * PAD_G + c] * sNb[k * 17 + c];
            a = a > 0.f ? a : 0.2f * a;
            m2 = fmaxf(m2, a);
        }
        sPm[g * 32 + o] = m1;
        sPm[128 + g * 32 + o] = m2;
        __syncthreads();

        if (tid < 32) {
            float v = fmaxf(fmaxf(sPm[tid], sPm[32 + tid]),
                            fmaxf(sPm[64 + tid], sPm[96 + tid]));
            sAll[tid] = v;
            float w2 = fmaxf(fmaxf(sPm[128 + tid], sPm[160 + tid]),
                             fmaxf(sPm[192 + tid], sPm[224 + tid]));
            sAll[32 + tid] = w2;
        } else if (tid < 48) {           // gmax over neighbor part
            int c = tid - 32;
            float m = -FLT_MAX;
            for (int k = 0; k < KNN; k++) m = fmaxf(m, sNb[k * 17 + c]);
            sAll[64 + c] = m;
        } else if (tid < 64) {           // gmax over center part = center
            sAll[80 + (tid - 48)] = sCtr[tid - 48];
        }
        __syncthreads();

        // decoder (96 -> 128, ReLU) + residual (64 -> 128, ReLU), add
        float acc = tDec[tid];
#pragma unroll
        for (int c = 0; c < 96; c++) acc += sWdec[tid * PAD_DEC + c] * sAll[c];
        float dv = fmaxf(acc, 0.f);
        float r = tRes[tid];
#pragma unroll
        for (int c = 0; c < 64; c++) r += sWres[tid * PAD_RES + c] * sX[c];
        r = fmaxf(r, 0.f);
        out[((size_t)(b * C_OUT + tid)) * N_PTS + n] = dv + r;
        __syncthreads();
    }
}

// ---------------- launch -----------------------------------------------------
extern "C" void kernel_launch(void* const* d_in, const int* in_sizes, int n_in,
                              void* d_out, int out_size)
{
    const float* x    = (const float*)d_in[0];
    const float* Wres = (const float*)d_in[1];
    const float* gres = (const float*)d_in[2];
    const float* bres = (const float*)d_in[3];
    const float* mres = (const float*)d_in[4];
    const float* vres = (const float*)d_in[5];
    const float* Wbot = (const float*)d_in[6];
    const float* gbot = (const float*)d_in[7];
    const float* bbot = (const float*)d_in[8];
    const float* mbot = (const float*)d_in[9];
    const float* vbot = (const float*)d_in[10];
    const float* Wg1  = (const float*)d_in[11];
    const float* gg1  = (const float*)d_in[12];
    const float* bg1  = (const float*)d_in[13];
    const float* mg1  = (const float*)d_in[14];
    const float* vg1  = (const float*)d_in[15];
    const float* Wg2  = (const float*)d_in[16];
    const float* gg2  = (const float*)d_in[17];
    const float* bg2  = (const float*)d_in[18];
    const float* mg2  = (const float*)d_in[19];
    const float* vg2  = (const float*)d_in[20];
    const float* Wdec = (const float*)d_in[21];
    const float* gdec = (const float*)d_in[22];
    const float* bdec = (const float*)d_in[23];
    const float* mdec = (const float*)d_in[24];
    const float* vdec = (const float*)d_in[25];
    float* out = (float*)d_out;

    size_t smem_final = (128 * PAD_RES + 128 * PAD_DEC + 2 * 32 * PAD_G +
                         4 * 128 + 4 * 32 + 64 + 16 + 20 * 17 + 96 + 256) * sizeof(float)
                        + KNN * sizeof(int);
    cudaFuncSetAttribute(k_final, cudaFuncAttributeMaxDynamicSharedMemorySize,
                         (int)smem_final);

    k_prep<<<(BATCH * N_PTS + 255) / 256, 256>>>(x, Wbot, gbot, bbot, mbot, vbot);
    k_dist<<<dim3(N_PTS / 64, N_PTS / 64, BATCH), 256>>>(x);
    k_topk<<<BATCH * N_PTS, 128>>>();
    k_final<<<dim3(N_PTS / NT, BATCH), 128, smem_final>>>(
        x,
        Wres, gres, bres, mres, vres,
        Wg1, gg1, bg1, mg1, vg1,
        Wg2, gg2, bg2, mg2, vg2,
        Wdec, gdec, bdec, mdec, vdec,
        out);
}

// round 4
// speedup vs baseline: 1.1469x; 1.1469x over previous
#include <cuda_runtime.h>
#include <math.h>
#include <float.h>

#define N_PTS 4096
#define BATCH 4
#define C_IN  64
#define C_OUT 128
#define KNN   20
#define C_BOT 16
#define EPSBN 1e-5f

// ---------------- scratch (device globals; no allocation) ----------------
__device__ float g_sq[BATCH * N_PTS];                       // 64 KB
__device__ float g_hb[BATCH * N_PTS * C_BOT];               // 1 MB, [B*N,16]
__device__ float g_d2[(size_t)BATCH * N_PTS * N_PTS];       // 256 MiB
__device__ int   g_idx[BATCH * N_PTS * KNN];                // 1.3 MB
__device__ float g_allf[(size_t)BATCH * N_PTS * 96];        // 25 MB, [B*N,96]
__device__ float g_Wt[160 * 128];                           // folded [k][o]
__device__ float g_bias[256];                               // tDec[128], tRes[128]

// ---------------- K1: sq norms + bottleneck conv (BN+ReLU), hb transposed ----
__global__ void k_prep(const float* __restrict__ x,
                       const float* __restrict__ Wb, const float* __restrict__ gb,
                       const float* __restrict__ bb, const float* __restrict__ mb,
                       const float* __restrict__ vb)
{
    __shared__ float sW[C_BOT][C_IN];
    __shared__ float sS[C_BOT], sT[C_BOT];
    int tid = threadIdx.x;
    if (tid < C_BOT) {
        float s = gb[tid] * rsqrtf(vb[tid] + EPSBN);
        sS[tid] = s;
        sT[tid] = bb[tid] - mb[tid] * s;
    }
    for (int e = tid; e < C_BOT * C_IN; e += blockDim.x)
        sW[e >> 6][e & 63] = Wb[e];
    __syncthreads();

    int g = blockIdx.x * blockDim.x + tid;      // 0 .. BATCH*N_PTS-1
    if (g >= BATCH * N_PTS) return;
    int b = g >> 12, n = g & (N_PTS - 1);
    const float* xp = x + (size_t)b * C_IN * N_PTS + n;

    float xc[C_IN];
    float sq = 0.f;
#pragma unroll
    for (int c = 0; c < C_IN; c++) {
        float v = xp[(size_t)c * N_PTS];
        xc[c] = v;
        sq += v * v;                 // same ascending-c order as GEMM dot
    }
    g_sq[g] = sq;

#pragma unroll
    for (int o = 0; o < C_BOT; o++) {
        float acc = 0.f;
#pragma unroll
        for (int c = 0; c < C_IN; c++) acc += sW[o][c] * xc[c];
        float h = acc * sS[o] + sT[o];
        g_hb[(size_t)g * C_BOT + o] = fmaxf(h, 0.f);
    }
}

// ---------------- K2: pairwise squared distances (tiled fp32 GEMM) ----------
__global__ void k_dist(const float* __restrict__ x)
{
    __shared__ float As[64][64];
    __shared__ float Bs[64][64];
    __shared__ float sqA[64], sqB[64];

    int b  = blockIdx.z;
    int bi = blockIdx.y;
    int bj = blockIdx.x;
    int tid = threadIdx.x;
    const float* xb = x + (size_t)b * C_IN * N_PTS;

    for (int e = tid; e < 64 * 64; e += 256) {
        int i = e & 63, k = e >> 6;
        As[k][i] = xb[(size_t)k * N_PTS + bi * 64 + i];
        Bs[k][i] = xb[(size_t)k * N_PTS + bj * 64 + i];
    }
    if (tid < 64)       sqA[tid]      = g_sq[b * N_PTS + bi * 64 + tid];
    else if (tid < 128) sqB[tid - 64] = g_sq[b * N_PTS + bj * 64 + (tid - 64)];
    __syncthreads();

    int tx = tid & 15, ty = tid >> 4;
    float acc[4][4] = {};
#pragma unroll 16
    for (int k = 0; k < 64; k++) {
        float a0 = As[k][ty * 4 + 0], a1 = As[k][ty * 4 + 1];
        float a2 = As[k][ty * 4 + 2], a3 = As[k][ty * 4 + 3];
        float b0 = Bs[k][tx * 4 + 0], b1 = Bs[k][tx * 4 + 1];
        float b2 = Bs[k][tx * 4 + 2], b3 = Bs[k][tx * 4 + 3];
        acc[0][0] += a0 * b0; acc[0][1] += a0 * b1; acc[0][2] += a0 * b2; acc[0][3] += a0 * b3;
        acc[1][0] += a1 * b0; acc[1][1] += a1 * b1; acc[1][2] += a1 * b2; acc[1][3] += a1 * b3;
        acc[2][0] += a2 * b0; acc[2][1] += a2 * b1; acc[2][2] += a2 * b2; acc[2][3] += a2 * b3;
        acc[3][0] += a3 * b0; acc[3][1] += a3 * b1; acc[3][2] += a3 * b2; acc[3][3] += a3 * b3;
    }

    float* dp = g_d2 + ((size_t)(b * N_PTS + bi * 64)) * N_PTS + bj * 64;
#pragma unroll
    for (int ri = 0; ri < 4; ri++) {
        int r = ty * 4 + ri;
        float sr = sqA[r];
        float4 v;
        v.x = sr + sqB[tx * 4 + 0] - 2.f * acc[ri][0];
        v.y = sr + sqB[tx * 4 + 1] - 2.f * acc[ri][1];
        v.z = sr + sqB[tx * 4 + 2] - 2.f * acc[ri][2];
        v.w = sr + sqB[tx * 4 + 3] - 2.f * acc[ri][3];
        *(float4*)(dp + (size_t)r * N_PTS + tx * 4) = v;
    }
}

// -------- K3: top-K via register keys + incremental min extraction ----------
__global__ void __launch_bounds__(128) k_topk()
{
    __shared__ unsigned long long sm4[4];
    int row = blockIdx.x;                      // b*N + n
    const float* dp = g_d2 + (size_t)row * N_PTS;
    int tid = threadIdx.x;                     // 128 threads, 32 elems each
    int lane = tid & 31, w = tid >> 5;

    unsigned kk[32];
    unsigned long long local = ~0ULL;
#pragma unroll
    for (int i = 0; i < 32; i++) {
        float d = dp[tid + i * 128];
        unsigned u = __float_as_uint(d);
        u = (u & 0x80000000u) ? ~u : (u | 0x80000000u);     // orderable key
        kk[i] = u;
        unsigned long long p = ((unsigned long long)u << 32) | (unsigned)(tid + i * 128);
        if (p < local) local = p;
    }

    for (int j = 0; j < KNN; j++) {
        unsigned long long v = local;
#pragma unroll
        for (int s = 16; s; s >>= 1) {
            unsigned long long o = __shfl_xor_sync(0xffffffffu, v, s);
            if (o < v) v = o;
        }
        if (lane == 0) sm4[w] = v;
        __syncthreads();
        unsigned long long best = sm4[0];
        if (sm4[1] < best) best = sm4[1];
        if (sm4[2] < best) best = sm4[2];
        if (sm4[3] < best) best = sm4[3];
        __syncthreads();

        int bi = (int)(best & 0xffffffffu);
        if (tid == 0) g_idx[row * KNN + j] = bi;
        if ((bi & 127) == tid) {                // owner: remove + recompute
            local = ~0ULL;
#pragma unroll
            for (int i = 0; i < 32; i++) {
                if (tid + i * 128 == bi) kk[i] = 0xFFFFFFFFu;
                unsigned long long p = ((unsigned long long)kk[i] << 32) |
                                       (unsigned)(tid + i * 128);
                if (p < local) local = p;
            }
        }
    }
}

// -------- K4a: fold decoder+residual weights (BN scale) into g_Wt -----------
__global__ void k_fold(const float* __restrict__ Wdec, const float* __restrict__ gdec,
                       const float* __restrict__ bdec, const float* __restrict__ mdec,
                       const float* __restrict__ vdec,
                       const float* __restrict__ Wres, const float* __restrict__ gres,
                       const float* __restrict__ bres, const float* __restrict__ mres,
                       const float* __restrict__ vres)
{
    int tid = blockIdx.x * blockDim.x + threadIdx.x;
    for (int e = tid; e < 160 * 128; e += gridDim.x * blockDim.x) {
        int k = e >> 7, o = e & 127;
        float wv;
        if (k < 96) wv = Wdec[o * 96 + k] * (gdec[o] * rsqrtf(vdec[o] + EPSBN));
        else        wv = Wres[o * 64 + (k - 96)] * (gres[o] * rsqrtf(vres[o] + EPSBN));
        g_Wt[e] = wv;
    }
    if (tid < 128) {
        float sd = gdec[tid] * rsqrtf(vdec[tid] + EPSBN);
        g_bias[tid] = bdec[tid] - mdec[tid] * sd;
        float sr = gres[tid] * rsqrtf(vres[tid] + EPSBN);
        g_bias[128 + tid] = bres[tid] - mres[tid] * sr;
    }
}

// -------- K4b: GCN branches + gmax, one warp per point ----------------------
__global__ void __launch_bounds__(256) k_gcn(
    const float* __restrict__ Wg1, const float* __restrict__ gg1,
    const float* __restrict__ bg1, const float* __restrict__ mg1,
    const float* __restrict__ vg1,
    const float* __restrict__ Wg2, const float* __restrict__ gg2,
    const float* __restrict__ bg2, const float* __restrict__ mg2,
    const float* __restrict__ vg2)
{
    __shared__ float sW1[32 * 33], sW2[32 * 33];
    __shared__ float sS1[32], sS2[32], t1[32], t2[32];
    __shared__ float sNb[8][KNN * 16];
    __shared__ float sCtr[8][16];

    int tid = threadIdx.x, lane = tid & 31, w = tid >> 5;

    if (tid < 32) {
        float s = gg1[tid] * rsqrtf(vg1[tid] + EPSBN);
        sS1[tid] = s; t1[tid] = bg1[tid] - mg1[tid] * s;
        s = gg2[tid] * rsqrtf(vg2[tid] + EPSBN);
        sS2[tid] = s; t2[tid] = bg2[tid] - mg2[tid] * s;
    }
    __syncthreads();
    for (int e = tid; e < 1024; e += 256) {
        int o = e >> 5, c = e & 31;
        sW1[o * 33 + c] = Wg1[e] * sS1[o];
        sW2[o * 33 + c] = Wg2[e] * sS2[o];
    }
    __syncthreads();

    int pt = blockIdx.x * 8 + w;                    // 0 .. B*N-1
    int b = pt >> 12;
    int idxv = (lane < KNN) ? g_idx[pt * KNN + lane] : 0;
    if (lane < 4)
        *(float4*)&sCtr[w][lane * 4] = *(const float4*)&g_hb[(size_t)pt * C_BOT + lane * 4];
#pragma unroll
    for (int t = 0; t < 3; t++) {                   // 80 float4 gathers
        int e = lane + t * 32;
        int row = (e < 80) ? (e >> 2) : 0;
        int ni = __shfl_sync(0xffffffffu, idxv, row);
        if (e < 80) {
            int q = e & 3;
            float4 v = *(const float4*)&g_hb[((size_t)(b << 12) + ni) * C_BOT + q * 4];
            *(float4*)&sNb[w][row * 16 + q * 4] = v;
        }
    }
    __syncwarp();

    float ctr[16];
#pragma unroll
    for (int c = 0; c < 16; c++) ctr[c] = sCtr[w][c];

    float cd1 = t1[lane], cd2 = t2[lane];
#pragma unroll
    for (int c = 0; c < 16; c++) {
        cd1 += sW1[lane * 33 + 16 + c] * ctr[c];
        cd2 += sW2[lane * 33 + 16 + c] * ctr[c];
    }
    float m1 = -FLT_MAX, m2 = -FLT_MAX;
#pragma unroll
    for (int k = 0; k < KNN; k++) {
        float a = cd1;
#pragma unroll
        for (int c = 0; c < 16; c++) a += sW1[lane * 33 + c] * sNb[w][k * 16 + c];
        a = a > 0.f ? a : 0.2f * a;
        m1 = fmaxf(m1, a);
        if ((k & 1) == 0) {
            float a2 = cd2;
#pragma unroll
            for (int c = 0; c < 16; c++) a2 += sW2[lane * 33 + c] * sNb[w][k * 16 + c];
            a2 = a2 > 0.f ? a2 : 0.2f * a2;
            m2 = fmaxf(m2, a2);
        }
    }
    float gm;
    if (lane < 16) {
        gm = -FLT_MAX;
#pragma unroll
        for (int k = 0; k < KNN; k++) gm = fmaxf(gm, sNb[w][k * 16 + lane]);
    } else {
        gm = ctr[lane - 16];
    }
    float* ap = g_allf + (size_t)pt * 96;
    ap[lane] = m1; ap[32 + lane] = m2; ap[64 + lane] = gm;
}

// -------- K4c: decoder+residual GEMM, 128o x 64n tiles ----------------------
#define FPAD 68
__global__ void __launch_bounds__(256) k_dec(const float* __restrict__ x,
                                             float* __restrict__ out)
{
    extern __shared__ float sm[];
    float* sW = sm;                     // 160*128
    float* sF = sW + 160 * 128;         // 16*FPAD
    float* sB = sF + 16 * FPAD;         // 256

    int tid = threadIdx.x;
    int b = blockIdx.y, n0 = blockIdx.x * 64;
    size_t gr0 = (size_t)b * N_PTS + n0;

    for (int e = tid; e < 160 * 128 / 4; e += 256)
        ((float4*)sW)[e] = ((const float4*)g_Wt)[e];
    sB[tid] = g_bias[tid];      // 256 threads cover 256
    __syncthreads();

    int to = tid & 31, tn = tid >> 5;   // o tile of 4, n tile of 8
    float acc[4][8];
    float res[4][8];

    // ---- phase 1: decoder, K=96 from allf ----
#pragma unroll
    for (int i = 0; i < 4; i++)
#pragma unroll
        for (int j = 0; j < 8; j++) acc[i][j] = 0.f;

    for (int kc = 0; kc < 6; kc++) {
        {
            int row = tid >> 2, q = tid & 3;
            float4 v = *(const float4*)&g_allf[(gr0 + row) * 96 + kc * 16 + q * 4];
            sF[(q * 4 + 0) * FPAD + row] = v.x;
            sF[(q * 4 + 1) * FPAD + row] = v.y;
            sF[(q * 4 + 2) * FPAD + row] = v.z;
            sF[(q * 4 + 3) * FPAD + row] = v.w;
        }
        __syncthreads();
#pragma unroll
        for (int k = 0; k < 16; k++) {
            float4 wv = *(float4*)&sW[(kc * 16 + k) * 128 + to * 4];
            float4 f0 = *(float4*)&sF[k * FPAD + tn * 8];
            float4 f1 = *(float4*)&sF[k * FPAD + tn * 8 + 4];
            float wr[4] = {wv.x, wv.y, wv.z, wv.w};
            float fr[8] = {f0.x, f0.y, f0.z, f0.w, f1.x, f1.y, f1.z, f1.w};
#pragma unroll
            for (int i = 0; i < 4; i++)
#pragma unroll
                for (int j = 0; j < 8; j++) acc[i][j] += wr[i] * fr[j];
        }
        __syncthreads();
    }
#pragma unroll
    for (int i = 0; i < 4; i++) {
        float bv = sB[to * 4 + i];
#pragma unroll
        for (int j = 0; j < 8; j++) {
            res[i][j] = fmaxf(acc[i][j] + bv, 0.f);
            acc[i][j] = 0.f;
        }
    }

    // ---- phase 2: residual, K=64 from x (coalesced channel rows) ----
    for (int kc = 0; kc < 4; kc++) {
        {
            int c = tid >> 4, nq = tid & 15;
            float4 v = *(const float4*)&x[((size_t)(b * C_IN + kc * 16 + c)) * N_PTS +
                                          n0 + nq * 4];
            *(float4*)&sF[c * FPAD + nq * 4] = v;
        }
        __syncthreads();
#pragma unroll
        for (int k = 0; k < 16; k++) {
            float4 wv = *(float4*)&sW[(96 + kc * 16 + k) * 128 + to * 4];
            float4 f0 = *(float4*)&sF[k * FPAD + tn * 8];
            float4 f1 = *(float4*)&sF[k * FPAD + tn * 8 + 4];
            float wr[4] = {wv.x, wv.y, wv.z, wv.w};
            float fr[8] = {f0.x, f0.y, f0.z, f0.w, f1.x, f1.y, f1.z, f1.w};
#pragma unroll
            for (int i = 0; i < 4; i++)
#pragma unroll
                for (int j = 0; j < 8; j++) acc[i][j] += wr[i] * fr[j];
        }
        __syncthreads();
    }

#pragma unroll
    for (int i = 0; i < 4; i++) {
        int o = to * 4 + i;
        float bv = sB[128 + o];
        float4 r0, r1;
        r0.x = res[i][0] + fmaxf(acc[i][0] + bv, 0.f);
        r0.y = res[i][1] + fmaxf(acc[i][1] + bv, 0.f);
        r0.z = res[i][2] + fmaxf(acc[i][2] + bv, 0.f);
        r0.w = res[i][3] + fmaxf(acc[i][3] + bv, 0.f);
        r1.x = res[i][4] + fmaxf(acc[i][4] + bv, 0.f);
        r1.y = res[i][5] + fmaxf(acc[i][5] + bv, 0.f);
        r1.z = res[i][6] + fmaxf(acc[i][6] + bv, 0.f);
        r1.w = res[i][7] + fmaxf(acc[i][7] + bv, 0.f);
        float* op = out + ((size_t)(b * C_OUT + o)) * N_PTS + n0 + tn * 8;
        *(float4*)op = r0;
        *(float4*)(op + 4) = r1;
    }
}

// ---------------- launch -----------------------------------------------------
extern "C" void kernel_launch(void* const* d_in, const int* in_sizes, int n_in,
                              void* d_out, int out_size)
{
    const float* x    = (const float*)d_in[0];
    const float* Wres = (const float*)d_in[1];
    const float* gres = (const float*)d_in[2];
    const float* bres = (const float*)d_in[3];
    const float* mres = (const float*)d_in[4];
    const float* vres = (const float*)d_in[5];
    const float* Wbot = (const float*)d_in[6];
    const float* gbot = (const float*)d_in[7];
    const float* bbot = (const float*)d_in[8];
    const float* mbot = (const float*)d_in[9];
    const float* vbot = (const float*)d_in[10];
    const float* Wg1  = (const float*)d_in[11];
    const float* gg1  = (const float*)d_in[12];
    const float* bg1  = (const float*)d_in[13];
    const float* mg1  = (const float*)d_in[14];
    const float* vg1  = (const float*)d_in[15];
    const float* Wg2  = (const float*)d_in[16];
    const float* gg2  = (const float*)d_in[17];
    const float* bg2  = (const float*)d_in[18];
    const float* mg2  = (const float*)d_in[19];
    const float* vg2  = (const float*)d_in[20];
    const float* Wdec = (const float*)d_in[21];
    const float* gdec = (const float*)d_in[22];
    const float* bdec = (const float*)d_in[23];
    const float* mdec = (const float*)d_in[24];
    const float* vdec = (const float*)d_in[25];
    float* out = (float*)d_out;

    size_t smem_dec = (160 * 128 + 16 * FPAD + 256) * sizeof(float);
    cudaFuncSetAttribute(k_dec, cudaFuncAttributeMaxDynamicSharedMemorySize,
                         (int)smem_dec);

    k_prep<<<(BATCH * N_PTS + 255) / 256, 256>>>(x, Wbot, gbot, bbot, mbot, vbot);
    k_fold<<<80, 256>>>(Wdec, gdec, bdec, mdec, vdec, Wres, gres, bres, mres, vres);
    k_dist<<<dim3(N_PTS / 64, N_PTS / 64, BATCH), 256>>>(x);
    k_topk<<<BATCH * N_PTS, 128>>>();
    k_gcn<<<BATCH * N_PTS / 8, 256>>>(Wg1, gg1, bg1, mg1, vg1,
                                      Wg2, gg2, bg2, mg2, vg2);
    k_dec<<<dim3(N_PTS / 64, BATCH), 256, smem_dec>>>(x, out);
}

// round 5
// speedup vs baseline: 2.4574x; 2.1426x over previous
#include <cuda_runtime.h>
#include <math.h>
#include <float.h>

#define N_PTS 4096
#define BATCH 4
#define C_IN  64
#define C_OUT 128
#define KNN   20
#define C_BOT 16
#define EPSBN 1e-5f

// ---------------- scratch (device globals; no allocation) ----------------
__device__ float g_sq[BATCH * N_PTS];                       // 64 KB
__device__ float g_hb[BATCH * N_PTS * C_BOT];               // 1 MB, [B*N,16]
__device__ float g_d2[(size_t)BATCH * N_PTS * N_PTS];       // 256 MiB
__device__ int   g_idx[BATCH * N_PTS * KNN];                // 1.3 MB
__device__ float g_allf[(size_t)BATCH * N_PTS * 96];        // 25 MB, [B*N,96]
__device__ float g_Wt[160 * 128];                           // folded [k][o]
__device__ float g_bias[256];                               // tDec[128], tRes[128]

// ---------------- f32x2 helpers (Blackwell packed FMA path) -----------------
__device__ __forceinline__ unsigned long long pk2(float x, float y) {
    unsigned long long r;
    asm("mov.b64 %0, {%1,%2};" : "=l"(r) : "f"(x), "f"(y));
    return r;
}
__device__ __forceinline__ void upk2(unsigned long long v, float& x, float& y) {
    asm("mov.b64 {%0,%1}, %2;" : "=f"(x), "=f"(y) : "l"(v));
}
__device__ __forceinline__ unsigned long long fma2(unsigned long long a,
                                                   unsigned long long b,
                                                   unsigned long long c) {
    unsigned long long d;
    asm("fma.rn.f32x2 %0, %1, %2, %3;" : "=l"(d) : "l"(a), "l"(b), "l"(c));
    return d;
}

// ---------------- K1: sq norms + bottleneck conv (BN+ReLU), hb transposed ----
__global__ void k_prep(const float* __restrict__ x,
                       const float* __restrict__ Wb, const float* __restrict__ gb,
                       const float* __restrict__ bb, const float* __restrict__ mb,
                       const float* __restrict__ vb)
{
    __shared__ float sW[C_BOT][C_IN];
    __shared__ float sS[C_BOT], sT[C_BOT];
    int tid = threadIdx.x;
    if (tid < C_BOT) {
        float s = gb[tid] * rsqrtf(vb[tid] + EPSBN);
        sS[tid] = s;
        sT[tid] = bb[tid] - mb[tid] * s;
    }
    for (int e = tid; e < C_BOT * C_IN; e += blockDim.x)
        sW[e >> 6][e & 63] = Wb[e];
    __syncthreads();

    int g = blockIdx.x * blockDim.x + tid;      // 0 .. BATCH*N_PTS-1
    if (g >= BATCH * N_PTS) return;
    int b = g >> 12, n = g & (N_PTS - 1);
    const float* xp = x + (size_t)b * C_IN * N_PTS + n;

    float xc[C_IN];
    float sq = 0.f;
#pragma unroll
    for (int c = 0; c < C_IN; c++) {
        float v = xp[(size_t)c * N_PTS];
        xc[c] = v;
        sq += v * v;                 // same ascending-c order as GEMM dot
    }
    g_sq[g] = sq;

#pragma unroll
    for (int o = 0; o < C_BOT; o++) {
        float acc = 0.f;
#pragma unroll
        for (int c = 0; c < C_IN; c++) acc += sW[o][c] * xc[c];
        float h = acc * sS[o] + sT[o];
        g_hb[(size_t)g * C_BOT + o] = fmaxf(h, 0.f);
    }
}

// ---------------- K2: pairwise squared distances (f32x2 tiled GEMM) ---------
__global__ void k_dist(const float* __restrict__ x)
{
    __shared__ float As[64][64];
    __shared__ float Bs[64][64];
    __shared__ float sqA[64], sqB[64];

    int b  = blockIdx.z;
    int bi = blockIdx.y;
    int bj = blockIdx.x;
    int tid = threadIdx.x;
    const float* xb = x + (size_t)b * C_IN * N_PTS;

    for (int e = tid; e < 64 * 64; e += 256) {
        int i = e & 63, k = e >> 6;
        As[k][i] = xb[(size_t)k * N_PTS + bi * 64 + i];
        Bs[k][i] = xb[(size_t)k * N_PTS + bj * 64 + i];
    }
    if (tid < 64)       sqA[tid]      = g_sq[b * N_PTS + bi * 64 + tid];
    else if (tid < 128) sqB[tid - 64] = g_sq[b * N_PTS + bj * 64 + (tid - 64)];
    __syncthreads();

    int tx = tid & 15, ty = tid >> 4;
    unsigned long long acc2[4][2];
#pragma unroll
    for (int i = 0; i < 4; i++) { acc2[i][0] = 0ULL; acc2[i][1] = 0ULL; }

#pragma unroll 16
    for (int k = 0; k < 64; k++) {
        float2 a01 = *(const float2*)&As[k][ty * 4];
        float2 a23 = *(const float2*)&As[k][ty * 4 + 2];
        float2 b01 = *(const float2*)&Bs[k][tx * 4];
        float2 b23 = *(const float2*)&Bs[k][tx * 4 + 2];
        unsigned long long B01 = pk2(b01.x, b01.y);
        unsigned long long B23 = pk2(b23.x, b23.y);
        unsigned long long A0 = pk2(a01.x, a01.x);
        unsigned long long A1 = pk2(a01.y, a01.y);
        unsigned long long A2 = pk2(a23.x, a23.x);
        unsigned long long A3 = pk2(a23.y, a23.y);
        acc2[0][0] = fma2(A0, B01, acc2[0][0]);
        acc2[0][1] = fma2(A0, B23, acc2[0][1]);
        acc2[1][0] = fma2(A1, B01, acc2[1][0]);
        acc2[1][1] = fma2(A1, B23, acc2[1][1]);
        acc2[2][0] = fma2(A2, B01, acc2[2][0]);
        acc2[2][1] = fma2(A2, B23, acc2[2][1]);
        acc2[3][0] = fma2(A3, B01, acc2[3][0]);
        acc2[3][1] = fma2(A3, B23, acc2[3][1]);
    }

    float* dp = g_d2 + ((size_t)(b * N_PTS + bi * 64)) * N_PTS + bj * 64;
#pragma unroll
    for (int ri = 0; ri < 4; ri++) {
        int r = ty * 4 + ri;
        float sr = sqA[r];
        float c0, c1, c2, c3;
        upk2(acc2[ri][0], c0, c1);
        upk2(acc2[ri][1], c2, c3);
        float4 v;
        v.x = sr + sqB[tx * 4 + 0] - 2.f * c0;
        v.y = sr + sqB[tx * 4 + 1] - 2.f * c1;
        v.z = sr + sqB[tx * 4 + 2] - 2.f * c2;
        v.w = sr + sqB[tx * 4 + 3] - 2.f * c3;
        *(float4*)(dp + (size_t)r * N_PTS + tx * 4) = v;
    }
}

// -------- K3: streaming top-K, one warp per row, warp insertion list --------
__global__ void __launch_bounds__(256) k_topk()
{
    int lane = threadIdx.x & 31, w = threadIdx.x >> 5;
    int row = blockIdx.x * 8 + w;              // b*N + n
    const float* dp = g_d2 + (size_t)row * N_PTS;

    // ---- chunk 0: load 32, pack, bitonic sort ascending ----
    float d0 = dp[lane];
    unsigned u0 = __float_as_uint(d0);
    u0 = (u0 & 0x80000000u) ? ~u0 : (u0 | 0x80000000u);
    unsigned long long p = ((unsigned long long)u0 << 32) | (unsigned)lane;

#pragma unroll
    for (int k2 = 2; k2 <= 32; k2 <<= 1) {
#pragma unroll
        for (int j = k2 >> 1; j > 0; j >>= 1) {
            unsigned long long q = __shfl_xor_sync(0xffffffffu, p, j);
            bool up = ((lane & k2) == 0);
            bool lower = ((lane & j) == 0);
            bool takeMin = (up == lower);
            bool qs = q < p;
            p = (takeMin == qs) ? q : p;
        }
    }

    unsigned thr_key = (unsigned)(__shfl_sync(0xffffffffu, p, 19) >> 32);

    // ---- chunks 1..127: filter + rare insertion ----
    float dnext = dp[32 + lane];
#pragma unroll 1
    for (int c = 1; c < 128; c++) {
        float dv = dnext;
        if (c < 127) dnext = dp[(c + 1) * 32 + lane];
        unsigned uk = __float_as_uint(dv);
        uk = (uk & 0x80000000u) ? ~uk : (uk | 0x80000000u);
        unsigned hit = __ballot_sync(0xffffffffu, uk < thr_key);
        while (hit) {
            int src = __ffs(hit) - 1;
            hit &= hit - 1;
            unsigned ks = __shfl_sync(0xffffffffu, uk, src);
            if (ks >= thr_key) continue;           // threshold tightened
            unsigned long long pn = ((unsigned long long)ks << 32) |
                                    (unsigned)(c * 32 + src);
            unsigned posmask = __ballot_sync(0xffffffffu, p < pn);
            int pos = __popc(posmask);             // list is sorted ascending
            unsigned long long sh = __shfl_up_sync(0xffffffffu, p, 1);
            if (lane == pos)      p = pn;
            else if (lane > pos)  p = sh;
            thr_key = (unsigned)(__shfl_sync(0xffffffffu, p, 19) >> 32);
        }
    }

    if (lane < KNN)
        g_idx[row * KNN + lane] = (int)(p & 0xFFFFFFFFULL);
}

// -------- K4a: fold decoder+residual weights (BN scale) into g_Wt -----------
__global__ void k_fold(const float* __restrict__ Wdec, const float* __restrict__ gdec,
                       const float* __restrict__ bdec, const float* __restrict__ mdec,
                       const float* __restrict__ vdec,
                       const float* __restrict__ Wres, const float* __restrict__ gres,
                       const float* __restrict__ bres, const float* __restrict__ mres,
                       const float* __restrict__ vres)
{
    int tid = blockIdx.x * blockDim.x + threadIdx.x;
    for (int e = tid; e < 160 * 128; e += gridDim.x * blockDim.x) {
        int k = e >> 7, o = e & 127;
        float wv;
        if (k < 96) wv = Wdec[o * 96 + k] * (gdec[o] * rsqrtf(vdec[o] + EPSBN));
        else        wv = Wres[o * 64 + (k - 96)] * (gres[o] * rsqrtf(vres[o] + EPSBN));
        g_Wt[e] = wv;
    }
    if (tid < 128) {
        float sd = gdec[tid] * rsqrtf(vdec[tid] + EPSBN);
        g_bias[tid] = bdec[tid] - mdec[tid] * sd;
        float sr = gres[tid] * rsqrtf(vres[tid] + EPSBN);
        g_bias[128 + tid] = bres[tid] - mres[tid] * sr;
    }
}

// -------- K4b: GCN branches + gmax, one warp per point ----------------------
__global__ void __launch_bounds__(256) k_gcn(
    const float* __restrict__ Wg1, const float* __restrict__ gg1,
    const float* __restrict__ bg1, const float* __restrict__ mg1,
    const float* __restrict__ vg1,
    const float* __restrict__ Wg2, const float* __restrict__ gg2,
    const float* __restrict__ bg2, const float* __restrict__ mg2,
    const float* __restrict__ vg2)
{
    __shared__ float sW1[32 * 33], sW2[32 * 33];
    __shared__ float sS1[32], sS2[32], t1[32], t2[32];
    __shared__ float sNb[8][KNN * 16];
    __shared__ float sCtr[8][16];

    int tid = threadIdx.x, lane = tid & 31, w = tid >> 5;

    if (tid < 32) {
        float s = gg1[tid] * rsqrtf(vg1[tid] + EPSBN);
        sS1[tid] = s; t1[tid] = bg1[tid] - mg1[tid] * s;
        s = gg2[tid] * rsqrtf(vg2[tid] + EPSBN);
        sS2[tid] = s; t2[tid] = bg2[tid] - mg2[tid] * s;
    }
    __syncthreads();
    for (int e = tid; e < 1024; e += 256) {
        int o = e >> 5, c = e & 31;
        sW1[o * 33 + c] = Wg1[e] * sS1[o];
        sW2[o * 33 + c] = Wg2[e] * sS2[o];
    }
    __syncthreads();

    int pt = blockIdx.x * 8 + w;                    // 0 .. B*N-1
    int b = pt >> 12;
    int idxv = (lane < KNN) ? g_idx[pt * KNN + lane] : 0;
    if (lane < 4)
        *(float4*)&sCtr[w][lane * 4] = *(const float4*)&g_hb[(size_t)pt * C_BOT + lane * 4];
#pragma unroll
    for (int t = 0; t < 3; t++) {                   // 80 float4 gathers
        int e = lane + t * 32;
        int row = (e < 80) ? (e >> 2) : 0;
        int ni = __shfl_sync(0xffffffffu, idxv, row);
        if (e < 80) {
            int q = e & 3;
            float4 v = *(const float4*)&g_hb[((size_t)(b << 12) + ni) * C_BOT + q * 4];
            *(float4*)&sNb[w][row * 16 + q * 4] = v;
        }
    }
    __syncwarp();

    float ctr[16];
#pragma unroll
    for (int c = 0; c < 16; c++) ctr[c] = sCtr[w][c];

    float cd1 = t1[lane], cd2 = t2[lane];
#pragma unroll
    for (int c = 0; c < 16; c++) {
        cd1 += sW1[lane * 33 + 16 + c] * ctr[c];
        cd2 += sW2[lane * 33 + 16 + c] * ctr[c];
    }
    float m1 = -FLT_MAX, m2 = -FLT_MAX;
#pragma unroll
    for (int k = 0; k < KNN; k++) {
        float a = cd1;
#pragma unroll
        for (int c = 0; c < 16; c++) a += sW1[lane * 33 + c] * sNb[w][k * 16 + c];
        a = a > 0.f ? a : 0.2f * a;
        m1 = fmaxf(m1, a);
        if ((k & 1) == 0) {
            float a2 = cd2;
#pragma unroll
            for (int c = 0; c < 16; c++) a2 += sW2[lane * 33 + c] * sNb[w][k * 16 + c];
            a2 = a2 > 0.f ? a2 : 0.2f * a2;
            m2 = fmaxf(m2, a2);
        }
    }
    float gm;
    if (lane < 16) {
        gm = -FLT_MAX;
#pragma unroll
        for (int k = 0; k < KNN; k++) gm = fmaxf(gm, sNb[w][k * 16 + lane]);
    } else {
        gm = ctr[lane - 16];
    }
    float* ap = g_allf + (size_t)pt * 96;
    ap[lane] = m1; ap[32 + lane] = m2; ap[64 + lane] = gm;
}

// -------- K4c: decoder+residual GEMM, 128o x 64n tiles ----------------------
#define FPAD 68
__global__ void __launch_bounds__(256) k_dec(const float* __restrict__ x,
                                             float* __restrict__ out)
{
    extern __shared__ float sm[];
    float* sW = sm;                     // 160*128
    float* sF = sW + 160 * 128;         // 16*FPAD
    float* sB = sF + 16 * FPAD;         // 256

    int tid = threadIdx.x;
    int b = blockIdx.y, n0 = blockIdx.x * 64;
    size_t gr0 = (size_t)b * N_PTS + n0;

    for (int e = tid; e < 160 * 128 / 4; e += 256)
        ((float4*)sW)[e] = ((const float4*)g_Wt)[e];
    sB[tid] = g_bias[tid];      // 256 threads cover 256
    __syncthreads();

    int to = tid & 31, tn = tid >> 5;   // o tile of 4, n tile of 8
    float acc[4][8];
    float res[4][8];

    // ---- phase 1: decoder, K=96 from allf ----
#pragma unroll
    for (int i = 0; i < 4; i++)
#pragma unroll
        for (int j = 0; j < 8; j++) acc[i][j] = 0.f;

    for (int kc = 0; kc < 6; kc++) {
        {
            int row = tid >> 2, q = tid & 3;
            float4 v = *(const float4*)&g_allf[(gr0 + row) * 96 + kc * 16 + q * 4];
            sF[(q * 4 + 0) * FPAD + row] = v.x;
            sF[(q * 4 + 1) * FPAD + row] = v.y;
            sF[(q * 4 + 2) * FPAD + row] = v.z;
            sF[(q * 4 + 3) * FPAD + row] = v.w;
        }
        __syncthreads();
#pragma unroll
        for (int k = 0; k < 16; k++) {
            float4 wv = *(float4*)&sW[(kc * 16 + k) * 128 + to * 4];
            float4 f0 = *(float4*)&sF[k * FPAD + tn * 8];
            float4 f1 = *(float4*)&sF[k * FPAD + tn * 8 + 4];
            float wr[4] = {wv.x, wv.y, wv.z, wv.w};
            float fr[8] = {f0.x, f0.y, f0.z, f0.w, f1.x, f1.y, f1.z, f1.w};
#pragma unroll
            for (int i = 0; i < 4; i++)
#pragma unroll
                for (int j = 0; j < 8; j++) acc[i][j] += wr[i] * fr[j];
        }
        __syncthreads();
    }
#pragma unroll
    for (int i = 0; i < 4; i++) {
        float bv = sB[to * 4 + i];
#pragma unroll
        for (int j = 0; j < 8; j++) {
            res[i][j] = fmaxf(acc[i][j] + bv, 0.f);
            acc[i][j] = 0.f;
        }
    }

    // ---- phase 2: residual, K=64 from x (coalesced channel rows) ----
    for (int kc = 0; kc < 4; kc++) {
        {
            int c = tid >> 4, nq = tid & 15;
            float4 v = *(const float4*)&x[((size_t)(b * C_IN + kc * 16 + c)) * N_PTS +
                                          n0 + nq * 4];
            *(float4*)&sF[c * FPAD + nq * 4] = v;
        }
        __syncthreads();
#pragma unroll
        for (int k = 0; k < 16; k++) {
            float4 wv = *(float4*)&sW[(96 + kc * 16 + k) * 128 + to * 4];
            float4 f0 = *(float4*)&sF[k * FPAD + tn * 8];
            float4 f1 = *(float4*)&sF[k * FPAD + tn * 8 + 4];
            float wr[4] = {wv.x, wv.y, wv.z, wv.w};
            float fr[8] = {f0.x, f0.y, f0.z, f0.w, f1.x, f1.y, f1.z, f1.w};
#pragma unroll
            for (int i = 0; i < 4; i++)
#pragma unroll
                for (int j = 0; j < 8; j++) acc[i][j] += wr[i] * fr[j];
        }
        __syncthreads();
    }

#pragma unroll
    for (int i = 0; i < 4; i++) {
        int o = to * 4 + i;
        float bv = sB[128 + o];
        float4 r0, r1;
        r0.x = res[i][0] + fmaxf(acc[i][0] + bv, 0.f);
        r0.y = res[i][1] + fmaxf(acc[i][1] + bv, 0.f);
        r0.z = res[i][2] + fmaxf(acc[i][2] + bv, 0.f);
        r0.w = res[i][3] + fmaxf(acc[i][3] + bv, 0.f);
        r1.x = res[i][4] + fmaxf(acc[i][4] + bv, 0.f);
        r1.y = res[i][5] + fmaxf(acc[i][5] + bv, 0.f);
        r1.z = res[i][6] + fmaxf(acc[i][6] + bv, 0.f);
        r1.w = res[i][7] + fmaxf(acc[i][7] + bv, 0.f);
        float* op = out + ((size_t)(b * C_OUT + o)) * N_PTS + n0 + tn * 8;
        *(float4*)op = r0;
        *(float4*)(op + 4) = r1;
    }
}

// ---------------- launch -----------------------------------------------------
extern "C" void kernel_launch(void* const* d_in, const int* in_sizes, int n_in,
                              void* d_out, int out_size)
{
    const float* x    = (const float*)d_in[0];
    const float* Wres = (const float*)d_in[1];
    const float* gres = (const float*)d_in[2];
    const float* bres = (const float*)d_in[3];
    const float* mres = (const float*)d_in[4];
    const float* vres = (const float*)d_in[5];
    const float* Wbot = (const float*)d_in[6];
    const float* gbot = (const float*)d_in[7];
    const float* bbot = (const float*)d_in[8];
    const float* mbot = (const float*)d_in[9];
    const float* vbot = (const float*)d_in[10];
    const float* Wg1  = (const float*)d_in[11];
    const float* gg1  = (const float*)d_in[12];
    const float* bg1  = (const float*)d_in[13];
    const float* mg1  = (const float*)d_in[14];
    const float* vg1  = (const float*)d_in[15];
    const float* Wg2  = (const float*)d_in[16];
    const float* gg2  = (const float*)d_in[17];
    const float* bg2  = (const float*)d_in[18];
    const float* mg2  = (const float*)d_in[19];
    const float* vg2  = (const float*)d_in[20];
    const float* Wdec = (const float*)d_in[21];
    const float* gdec = (const float*)d_in[22];
    const float* bdec = (const float*)d_in[23];
    const float* mdec = (const float*)d_in[24];
    const float* vdec = (const float*)d_in[25];
    float* out = (float*)d_out;

    size_t smem_dec = (160 * 128 + 16 * FPAD + 256) * sizeof(float);
    cudaFuncSetAttribute(k_dec, cudaFuncAttributeMaxDynamicSharedMemorySize,
                         (int)smem_dec);

    k_prep<<<(BATCH * N_PTS + 255) / 256, 256>>>(x, Wbot, gbot, bbot, mbot, vbot);
    k_fold<<<80, 256>>>(Wdec, gdec, bdec, mdec, vdec, Wres, gres, bres, mres, vres);
    k_dist<<<dim3(N_PTS / 64, N_PTS / 64, BATCH), 256>>>(x);
    k_topk<<<BATCH * N_PTS / 8, 256>>>();
    k_gcn<<<BATCH * N_PTS / 8, 256>>>(Wg1, gg1, bg1, mg1, vg1,
                                      Wg2, gg2, bg2, mg2, vg2);
    k_dec<<<dim3(N_PTS / 64, BATCH), 256, smem_dec>>>(x, out);
}